// round 1
// baseline (speedup 1.0000x reference)
#include <cuda_runtime.h>
#include <math.h>

// Problem constants
#define NN   32768
#define EE   262144
#define FF   64
#define ZZ   10
#define NBB  8
#define LL   2
#define HH   16

static __device__ __constant__ const float EPSC   = 0.24253562503633297f;  // 1/sqrt(17)
static __device__ __constant__ const float SQRT2  = 1.4142135623730951f;
static __device__ __constant__ const float PI_F   = 3.14159265358979323846f;

// Scratch (device globals; allocation-free)
__device__ float g_sA[NN * FF];
__device__ float g_vA[NN * 3 * FF];
__device__ float g_sB[NN * FF];
__device__ float g_vB[NN * 3 * FF];
__device__ float g_aggS[NN * FF];
__device__ float g_aggV[NN * 3 * FF];

// ---------------------------------------------------------------------------
// Init: s = embed_s[spec], v = 0, agg = 0
// grid covers NN*FF threads
// ---------------------------------------------------------------------------
__global__ void initK(const float* __restrict__ embed, const int* __restrict__ spec) {
    int i = blockIdx.x * 256 + threadIdx.x;
    if (i >= NN * FF) return;
    int n = i >> 6;
    int f = i & 63;
    g_sA[i] = embed[spec[n] * FF + f];
    g_aggS[i] = 0.f;
#pragma unroll
    for (int k = 0; k < 3; k++) {
        g_vA[(n * 3 + k) * FF + f] = 0.f;
        g_aggV[(n * 3 + k) * FF + f] = 0.f;
    }
}

// ---------------------------------------------------------------------------
// Edge kernel: fused bessel -> radial weights -> gather -> CG messages -> atomic scatter
// 256 threads = 4 edges x 64 channels
// ---------------------------------------------------------------------------
template <bool FIRST>
__global__ void edgeK(const float* __restrict__ vec,
                      const float* __restrict__ WrL,      // [8, 320] for this layer
                      const int*   __restrict__ snd,
                      const int*   __restrict__ rcv,
                      const float* __restrict__ sIn,      // [N,F]
                      const float* __restrict__ vIn) {    // [N,3,F]
    __shared__ float WrS[NBB * 5 * FF];   // 2560 floats = 10KB
    int t = threadIdx.x;
    for (int i = t; i < NBB * 5 * FF; i += 256) WrS[i] = WrL[i];
    __syncthreads();

    int e = blockIdx.x * 4 + (t >> 6);
    if (e >= EE) return;
    int f = t & 63;

    int s_ = snd[e];
    int r_ = rcv[e];
    float vx = vec[e * 3 + 0];
    float vy = vec[e * 3 + 1];
    float vz = vec[e * 3 + 2];

    float r = sqrtf(vx * vx + vy * vy + vz * vz + 1e-12f);
    float rc = fmaxf(r, 1e-6f);

    // polynomial envelope, p=6:  1 - 28 r^6 + 48 r^7 - 21 r^8  (0 for r>=1)
    float env = 0.f;
    if (r < 1.f) {
        float r2 = r * r;
        float r3 = r2 * r;
        float r6 = r3 * r3;
        env = 1.f - 28.f * r6 + 48.f * r6 * r - 21.f * r6 * r2;
    }
    float invrc = 1.f / rc;
    float scale = SQRT2 * invrc * env;

    // sin(n*pi*rc) via sincos + Chebyshev recurrence (arg in (0,pi): MUFU accurate)
    float x = PI_F * rc;
    float s1, c1;
    __sincosf(x, &s1, &c1);
    float c2 = 2.f * c1;
    float rb[NBB];
    rb[0] = s1;
    float sp = s1, spp = 0.f;
#pragma unroll
    for (int n = 1; n < NBB; n++) {
        float sn = c2 * sp - spp;
        rb[n] = sn;
        spp = sp;
        sp = sn;
    }
#pragma unroll
    for (int n = 0; n < NBB; n++) rb[n] *= scale;

    // radial weights: w[p] = sum_n rb[n] * Wr[n, p*64 + f]
    float w[5];
#pragma unroll
    for (int p = 0; p < 5; p++) {
        float a = 0.f;
#pragma unroll
        for (int n = 0; n < NBB; n++)
            a = fmaf(rb[n], WrS[n * 320 + p * 64 + f], a);
        w[p] = a;
    }

    float iy = 1.f / r;
    float y0 = vx * iy, y1 = vy * iy, y2 = vz * iy;

    float ss = sIn[s_ * FF + f];

    float m0, m1x, m1y, m1z;
    if (FIRST) {
        // v == 0: dot = 0, cross = 0, vs = 0
        m0 = w[0] * ss;
        float c = w[2] * ss;
        m1x = c * y0;
        m1y = c * y1;
        m1z = c * y2;
    } else {
        float vsx = vIn[(s_ * 3 + 0) * FF + f];
        float vsy = vIn[(s_ * 3 + 1) * FF + f];
        float vsz = vIn[(s_ * 3 + 2) * FF + f];
        float dot = vsx * y0 + vsy * y1 + vsz * y2;
        m0 = w[0] * ss + w[1] * dot;
        float cx = vsy * y2 - vsz * y1;
        float cy = vsz * y0 - vsx * y2;
        float cz = vsx * y1 - vsy * y0;
        float c = w[2] * ss;
        m1x = c * y0 + w[3] * vsx + w[4] * cx;
        m1y = c * y1 + w[3] * vsy + w[4] * cy;
        m1z = c * y2 + w[3] * vsz + w[4] * cz;
    }

    atomicAdd(&g_aggS[r_ * FF + f], m0);
    atomicAdd(&g_aggV[(r_ * 3 + 0) * FF + f], m1x);
    atomicAdd(&g_aggV[(r_ * 3 + 1) * FF + f], m1y);
    atomicAdd(&g_aggV[(r_ * 3 + 2) * FF + f], m1z);
}

// ---------------------------------------------------------------------------
// Node kernel: s2/v2 GEMMs, skip (layer>0), product basis, Wps/Wpv GEMMs, readout
// 256 threads = 4 nodes x 64 channels
// ---------------------------------------------------------------------------
template <int LAYER>
__global__ void nodeK(const float* __restrict__ sOld,   // [N,F]
                      const float* __restrict__ vOld,   // [N,3,F]
                      float* __restrict__ sNew,
                      float* __restrict__ vNew,
                      const int*   __restrict__ spec,
                      const float* __restrict__ WlsL,   // [F,F]
                      const float* __restrict__ WlvL,
                      const float* __restrict__ pwL,    // [Z,9,F]
                      const float* __restrict__ WpsL,
                      const float* __restrict__ WpvL,
                      const float* __restrict__ skipS,  // [Z,F,F]
                      const float* __restrict__ skipV,
                      const float* __restrict__ Wread0, // [F]
                      const float* __restrict__ Wr1a,   // [F,H]
                      const float* __restrict__ Wr1b,   // [H]
                      float* __restrict__ out) {
    __shared__ float Wb0[FF * FF];        // 16KB (Wls then Wps)
    __shared__ float Wb1[FF * FF];        // 16KB (Wlv then Wpv)
    __shared__ float aggR[4][FF];
    __shared__ float aggVR[4][3][FF];
    __shared__ float oldS[4][FF];
    __shared__ float oldV[4][3][FF];
    __shared__ float psS[4][FF];
    __shared__ float pvS[4][3][FF];
    __shared__ float sNS[4][FF];
    __shared__ float hS[4][HH];

    int t = threadIdx.x;
    int nl = t >> 6;
    int f = t & 63;
    int n = blockIdx.x * 4 + nl;

    // Phase 0: load weights + rows
    for (int i = t; i < FF * FF; i += 256) {
        Wb0[i] = WlsL[i];
        Wb1[i] = WlvL[i];
    }
    aggR[nl][f] = g_aggS[n * FF + f] * EPSC;
#pragma unroll
    for (int k = 0; k < 3; k++)
        aggVR[nl][k][f] = g_aggV[(n * 3 + k) * FF + f] * EPSC;
    if (LAYER == 0) {
        // zero accumulators for next layer's edge pass
        g_aggS[n * FF + f] = 0.f;
#pragma unroll
        for (int k = 0; k < 3; k++) g_aggV[(n * 3 + k) * FF + f] = 0.f;
    }
    if (LAYER > 0) {
        oldS[nl][f] = sOld[n * FF + f];
#pragma unroll
        for (int k = 0; k < 3; k++) oldV[nl][k][f] = vOld[(n * 3 + k) * FF + f];
    }
    __syncthreads();

    // Phase 1: s2 = agg_s @ Wls ; v2 = agg_v @ Wlv   (thread index = output channel)
    float s2 = 0.f, v2x = 0.f, v2y = 0.f, v2z = 0.f;
#pragma unroll 8
    for (int j = 0; j < FF; j++) {
        float wls = Wb0[j * FF + f];
        float wlv = Wb1[j * FF + f];
        s2  = fmaf(aggR[nl][j], wls, s2);
        v2x = fmaf(aggVR[nl][0][j], wlv, v2x);
        v2y = fmaf(aggVR[nl][1][j], wlv, v2y);
        v2z = fmaf(aggVR[nl][2][j], wlv, v2z);
    }

    int z = spec[n];

    // Skip connection (per-species linear on pre-interaction features)
    float scS = 0.f, scVx = 0.f, scVy = 0.f, scVz = 0.f;
    if (LAYER > 0) {
        const float* Ss = skipS + z * FF * FF;
        const float* Sv = skipV + z * FF * FF;
#pragma unroll 8
        for (int j = 0; j < FF; j++) {
            float a = Ss[j * FF + f];
            float b = Sv[j * FF + f];
            scS  = fmaf(oldS[nl][j], a, scS);
            scVx = fmaf(oldV[nl][0][j], b, scVx);
            scVy = fmaf(oldV[nl][1][j], b, scVy);
            scVz = fmaf(oldV[nl][2][j], b, scVz);
        }
    }

    // Product basis (elementwise per channel, thread holds its own channel)
    const float* pp = pwL + z * 9 * FF;
    float p0 = pp[0 * FF + f], p1 = pp[1 * FF + f], p2 = pp[2 * FF + f];
    float p3 = pp[3 * FF + f], p4 = pp[4 * FF + f], p5 = pp[5 * FF + f];
    float p6 = pp[6 * FF + f], p7 = pp[7 * FF + f], p8 = pp[8 * FF + f];
    float vv = v2x * v2x + v2y * v2y + v2z * v2z;
    float s2sq = s2 * s2;
    float ps = p0 * s2 + p1 * s2sq + p2 * vv + p3 * s2sq * s2 + p4 * s2 * vv;
    float pf = p5 + p6 * s2 + p7 * s2sq + p8 * vv;
    psS[nl][f] = ps;
    pvS[nl][0][f] = pf * v2x;
    pvS[nl][1][f] = pf * v2y;
    pvS[nl][2][f] = pf * v2z;
    __syncthreads();

    // Phase 2: swap weights -> Wps / Wpv
    for (int i = t; i < FF * FF; i += 256) {
        Wb0[i] = WpsL[i];
        Wb1[i] = WpvL[i];
    }
    __syncthreads();

    float sN = scS, vNx = scVx, vNy = scVy, vNz = scVz;
#pragma unroll 8
    for (int j = 0; j < FF; j++) {
        float wps = Wb0[j * FF + f];
        float wpv = Wb1[j * FF + f];
        sN  = fmaf(psS[nl][j], wps, sN);
        vNx = fmaf(pvS[nl][0][j], wpv, vNx);
        vNy = fmaf(pvS[nl][1][j], wpv, vNy);
        vNz = fmaf(pvS[nl][2][j], wpv, vNz);
    }

    if (LAYER < LL - 1) {
        sNew[n * FF + f] = sN;
        vNew[(n * 3 + 0) * FF + f] = vNx;
        vNew[(n * 3 + 1) * FF + f] = vNy;
        vNew[(n * 3 + 2) * FF + f] = vNz;
    }
    sNS[nl][f] = sN;
    __syncthreads();

    // Readout
    if (LAYER == 0) {
        if (f == 0) {
            float a = 0.f;
#pragma unroll 8
            for (int g = 0; g < FF; g++) a = fmaf(sNS[nl][g], Wread0[g], a);
            out[n * LL + 0] = a;
        }
    } else {
        if (f < HH) {
            float a = 0.f;
#pragma unroll 8
            for (int g = 0; g < FF; g++) a = fmaf(sNS[nl][g], Wr1a[g * HH + f], a);
            // silu
            hS[nl][f] = a / (1.f + __expf(-a));
        }
        __syncthreads();
        if (f == 0) {
            float a = 0.f;
#pragma unroll
            for (int j = 0; j < HH; j++) a = fmaf(hS[nl][j], Wr1b[j], a);
            out[n * LL + (LL - 1)] = a;
        }
    }
}

// ---------------------------------------------------------------------------
extern "C" void kernel_launch(void* const* d_in, const int* in_sizes, int n_in,
                              void* d_out, int out_size) {
    const float* vectors = (const float*)d_in[0];    // [E,3]
    const float* embed_s = (const float*)d_in[1];    // [Z,F]
    const float* Wr      = (const float*)d_in[2];    // [L,8,320]
    const float* Wls     = (const float*)d_in[3];    // [L,F,F]
    const float* Wlv     = (const float*)d_in[4];
    const float* skip_s  = (const float*)d_in[5];    // [Z,F,F]
    const float* skip_v  = (const float*)d_in[6];
    const float* pw      = (const float*)d_in[7];    // [L,Z,9,F]
    const float* Wps     = (const float*)d_in[8];    // [L,F,F]
    const float* Wpv     = (const float*)d_in[9];
    const float* Wread0  = (const float*)d_in[10];   // [F,1]
    const float* Wr1a    = (const float*)d_in[11];   // [F,H]
    const float* Wr1b    = (const float*)d_in[12];   // [H,1]
    const int*   senders   = (const int*)d_in[13];
    const int*   receivers = (const int*)d_in[14];
    const int*   species   = (const int*)d_in[15];
    float* out = (float*)d_out;

    void *p_sA, *p_vA, *p_sB, *p_vB;
    cudaGetSymbolAddress(&p_sA, g_sA);
    cudaGetSymbolAddress(&p_vA, g_vA);
    cudaGetSymbolAddress(&p_sB, g_sB);
    cudaGetSymbolAddress(&p_vB, g_vB);
    float* sA = (float*)p_sA;
    float* vA = (float*)p_vA;
    float* sB = (float*)p_sB;
    float* vB = (float*)p_vB;

    // init: embed + zero v + zero agg
    initK<<<(NN * FF) / 256, 256>>>(embed_s, species);

    // ---- Layer 0 ----
    edgeK<true><<<EE / 4, 256>>>(vectors, Wr + 0 * NBB * 5 * FF,
                                 senders, receivers, sA, vA);
    nodeK<0><<<NN / 4, 256>>>(sA, vA, sB, vB, species,
                              Wls + 0 * FF * FF, Wlv + 0 * FF * FF,
                              pw + 0 * ZZ * 9 * FF,
                              Wps + 0 * FF * FF, Wpv + 0 * FF * FF,
                              skip_s, skip_v, Wread0, Wr1a, Wr1b, out);

    // ---- Layer 1 ----
    edgeK<false><<<EE / 4, 256>>>(vectors, Wr + 1 * NBB * 5 * FF,
                                  senders, receivers, sB, vB);
    nodeK<1><<<NN / 4, 256>>>(sB, vB, sA, vA, species,
                              Wls + 1 * FF * FF, Wlv + 1 * FF * FF,
                              pw + 1 * ZZ * 9 * FF,
                              Wps + 1 * FF * FF, Wpv + 1 * FF * FF,
                              skip_s, skip_v, Wread0, Wr1a, Wr1b, out);
}

// round 2
// speedup vs baseline: 2.0807x; 2.0807x over previous
#include <cuda_runtime.h>
#include <math.h>

#define NN   32768
#define EE   262144
#define FF   64
#define ZZ   10
#define NBB  8
#define LL   2
#define HH   16

#define EPSC   0.24253562503633297f
#define SQRT2C 1.4142135623730951f
#define PI_F   3.14159265358979323846f

// Scratch (device globals; allocation-free), 16B-aligned for float4 access
__device__ __align__(16) float g_sA[NN * FF];
__device__ __align__(16) float g_vA[NN * 3 * FF];
__device__ __align__(16) float g_sB[NN * FF];
__device__ __align__(16) float g_vB[NN * 3 * FF];
__device__ __align__(16) float g_aggS[NN * FF];
__device__ __align__(16) float g_aggV[NN * 3 * FF];

__device__ __forceinline__ void redAdd4(float* p, float a, float b, float c, float d) {
    asm volatile("red.global.add.v4.f32 [%0], {%1, %2, %3, %4};"
                 :: "l"(p), "f"(a), "f"(b), "f"(c), "f"(d) : "memory");
}

// ---------------------------------------------------------------------------
// Init: s = embed_s[spec], v = 0, agg = 0   (float4 wide)
// ---------------------------------------------------------------------------
__global__ void initK(const float* __restrict__ embed, const int* __restrict__ spec) {
    int i = blockIdx.x * 256 + threadIdx.x;          // float4 index over [N*F/4]
    if (i >= NN * FF / 4) return;
    int n  = i >> 4;      // 16 float4 per node
    int f4 = i & 15;
    const float4* e4 = (const float4*)embed;
    ((float4*)g_sA)[i] = e4[spec[n] * 16 + f4];
    float4 z = make_float4(0.f, 0.f, 0.f, 0.f);
    ((float4*)g_aggS)[i] = z;
#pragma unroll
    for (int k = 0; k < 3; k++) {
        ((float4*)g_vA)[(n * 3 + k) * 16 + f4]   = z;
        ((float4*)g_aggV)[(n * 3 + k) * 16 + f4] = z;
    }
}

// ---------------------------------------------------------------------------
// Edge kernel: 16 edges/block x 16 threads/edge, 4 channels per thread (float4)
// ---------------------------------------------------------------------------
template <bool FIRST>
__global__ void edgeK(const float* __restrict__ vec,
                      const float* __restrict__ WrL,      // [8,320]
                      const int*   __restrict__ snd,
                      const int*   __restrict__ rcv,
                      const float* __restrict__ sIn,      // [N,F]
                      const float* __restrict__ vIn) {    // [N,3,F]
    __shared__ float WrS[NBB * 5 * FF];   // 2560 floats = 10KB
    int t = threadIdx.x;
    {
        const float4* src = (const float4*)WrL;
        float4* dst = (float4*)WrS;
        for (int i = t; i < NBB * 5 * FF / 4; i += 256) dst[i] = src[i];
    }
    __syncthreads();

    int e  = blockIdx.x * 16 + (t >> 4);
    int fi = t & 15;                      // channel group: channels 4*fi..4*fi+3

    int s_ = snd[e];
    int r_ = rcv[e];
    float vx = vec[e * 3 + 0];
    float vy = vec[e * 3 + 1];
    float vz = vec[e * 3 + 2];

    float r  = sqrtf(vx * vx + vy * vy + vz * vz + 1e-12f);
    float rc = fmaxf(r, 1e-6f);

    // envelope p=6: 1 - 28 r^6 + 48 r^7 - 21 r^8 (0 for r>=1)
    float env = 0.f;
    if (r < 1.f) {
        float r2 = r * r;
        float r6 = r2 * r2 * r2;
        env = 1.f - 28.f * r6 + 48.f * r6 * r - 21.f * r6 * r2;
    }
    float scale = SQRT2C * env / rc;

    // sin(n*pi*rc) via sincos + Chebyshev recurrence
    float s1, c1;
    __sincosf(PI_F * rc, &s1, &c1);
    float c2 = 2.f * c1;
    float rb[NBB];
    rb[0] = s1;
    float sp = s1, spp = 0.f;
#pragma unroll
    for (int n = 1; n < NBB; n++) {
        float sn = c2 * sp - spp;
        rb[n] = sn; spp = sp; sp = sn;
    }
#pragma unroll
    for (int n = 0; n < NBB; n++) rb[n] *= scale;

    // radial weights w[p] (float4 across channels)
    float4 w[5];
#pragma unroll
    for (int p = 0; p < 5; p++) {
        float4 a = make_float4(0.f, 0.f, 0.f, 0.f);
#pragma unroll
        for (int n = 0; n < NBB; n++) {
            float4 ww = *(const float4*)&WrS[n * 320 + p * 64 + fi * 4];
            a.x = fmaf(rb[n], ww.x, a.x);
            a.y = fmaf(rb[n], ww.y, a.y);
            a.z = fmaf(rb[n], ww.z, a.z);
            a.w = fmaf(rb[n], ww.w, a.w);
        }
        w[p] = a;
    }

    float iy = 1.f / r;
    float y0 = vx * iy, y1 = vy * iy, y2 = vz * iy;

    float4 ss = *(const float4*)&sIn[s_ * FF + fi * 4];

    float4 m0, m1x, m1y, m1z;
    if (FIRST) {
        m0.x = w[0].x * ss.x; m0.y = w[0].y * ss.y; m0.z = w[0].z * ss.z; m0.w = w[0].w * ss.w;
        float4 c;
        c.x = w[2].x * ss.x; c.y = w[2].y * ss.y; c.z = w[2].z * ss.z; c.w = w[2].w * ss.w;
        m1x.x = c.x * y0; m1x.y = c.y * y0; m1x.z = c.z * y0; m1x.w = c.w * y0;
        m1y.x = c.x * y1; m1y.y = c.y * y1; m1y.z = c.z * y1; m1y.w = c.w * y1;
        m1z.x = c.x * y2; m1z.y = c.y * y2; m1z.z = c.z * y2; m1z.w = c.w * y2;
    } else {
        float4 vsx = *(const float4*)&vIn[(s_ * 3 + 0) * FF + fi * 4];
        float4 vsy = *(const float4*)&vIn[(s_ * 3 + 1) * FF + fi * 4];
        float4 vsz = *(const float4*)&vIn[(s_ * 3 + 2) * FF + fi * 4];
#pragma unroll
        for (int c = 0; c < 4; c++) {
            float VX = (&vsx.x)[c], VY = (&vsy.x)[c], VZ = (&vsz.x)[c];
            float SS = (&ss.x)[c];
            float dot = VX * y0 + VY * y1 + VZ * y2;
            (&m0.x)[c] = w[0].x * 0.f; // placeholder overwritten below
            float w0 = (&w[0].x)[c], w1 = (&w[1].x)[c], w2 = (&w[2].x)[c];
            float w3 = (&w[3].x)[c], w4 = (&w[4].x)[c];
            (&m0.x)[c]  = w0 * SS + w1 * dot;
            float cc = w2 * SS;
            (&m1x.x)[c] = cc * y0 + w3 * VX + w4 * (VY * y2 - VZ * y1);
            (&m1y.x)[c] = cc * y1 + w3 * VY + w4 * (VZ * y0 - VX * y2);
            (&m1z.x)[c] = cc * y2 + w3 * VZ + w4 * (VX * y1 - VY * y0);
        }
    }

    redAdd4(&g_aggS[r_ * FF + fi * 4], m0.x, m0.y, m0.z, m0.w);
    redAdd4(&g_aggV[(r_ * 3 + 0) * FF + fi * 4], m1x.x, m1x.y, m1x.z, m1x.w);
    redAdd4(&g_aggV[(r_ * 3 + 1) * FF + fi * 4], m1y.x, m1y.y, m1y.z, m1y.w);
    redAdd4(&g_aggV[(r_ * 3 + 2) * FF + fi * 4], m1z.x, m1z.y, m1z.z, m1z.w);
}

// ---------------------------------------------------------------------------
// Node kernel: 16 nodes/block x 16 threads/node (4 channels each, float4)
// Dynamic smem layout (floats):
//   Wb0[4096] | Wb1[4096] | A_s[16*64] | A_v[16*3*64] | B_s[16*64] | B_v[16*3*64]
// ---------------------------------------------------------------------------
template <int LAYER>
__global__ void nodeK(const float* __restrict__ sOld,
                      const float* __restrict__ vOld,
                      float* __restrict__ sNew,
                      float* __restrict__ vNew,
                      const int*   __restrict__ spec,
                      const float* __restrict__ WlsL,
                      const float* __restrict__ WlvL,
                      const float* __restrict__ pwL,    // [Z,9,F]
                      const float* __restrict__ WpsL,
                      const float* __restrict__ WpvL,
                      const float* __restrict__ skipS,  // [Z,F,F]
                      const float* __restrict__ skipV,
                      const float* __restrict__ Wread0,
                      const float* __restrict__ Wr1a,   // [F,H]
                      const float* __restrict__ Wr1b,   // [H]
                      float* __restrict__ out) {
    extern __shared__ float sm[];
    float* Wb0 = sm;                 // 4096
    float* Wb1 = sm + 4096;          // 4096
    float* A_s = sm + 8192;          // 1024
    float* A_v = sm + 9216;          // 3072
    float* B_s = sm + 12288;         // 1024
    float* B_v = sm + 13312;         // 3072  (total 16384 floats = 64KB)

    int t  = threadIdx.x;
    int nl = t >> 4;
    int fi = t & 15;
    int n  = blockIdx.x * 16 + nl;

    // Phase 0: load Wls/Wlv + agg rows (+old rows for skip)
    {
        const float4* a4 = (const float4*)WlsL;
        const float4* b4 = (const float4*)WlvL;
        float4* d0 = (float4*)Wb0;
        float4* d1 = (float4*)Wb1;
        for (int i = t; i < 1024; i += 256) { d0[i] = a4[i]; d1[i] = b4[i]; }
    }
    {
        float4 a = ((const float4*)g_aggS)[n * 16 + fi];
        a.x *= EPSC; a.y *= EPSC; a.z *= EPSC; a.w *= EPSC;
        *(float4*)&A_s[nl * 64 + fi * 4] = a;
#pragma unroll
        for (int k = 0; k < 3; k++) {
            float4 v = ((const float4*)g_aggV)[(n * 3 + k) * 16 + fi];
            v.x *= EPSC; v.y *= EPSC; v.z *= EPSC; v.w *= EPSC;
            *(float4*)&A_v[(nl * 3 + k) * 64 + fi * 4] = v;
        }
        float4 z = make_float4(0.f, 0.f, 0.f, 0.f);
        if (LAYER == 0) {
            ((float4*)g_aggS)[n * 16 + fi] = z;
#pragma unroll
            for (int k = 0; k < 3; k++) ((float4*)g_aggV)[(n * 3 + k) * 16 + fi] = z;
        }
        if (LAYER > 0) {
            *(float4*)&B_s[nl * 64 + fi * 4] = ((const float4*)sOld)[n * 16 + fi];
#pragma unroll
            for (int k = 0; k < 3; k++)
                *(float4*)&B_v[(nl * 3 + k) * 64 + fi * 4] =
                    ((const float4*)vOld)[(n * 3 + k) * 16 + fi];
        }
    }
    __syncthreads();

    // Phase 1: s2 = agg_s @ Wls ; v2 = agg_v @ Wlv
    float4 s2  = make_float4(0.f, 0.f, 0.f, 0.f);
    float4 v2x = s2, v2y = s2, v2z = s2;
#pragma unroll 4
    for (int j = 0; j < FF; j++) {
        float a  = A_s[nl * 64 + j];
        float ax = A_v[(nl * 3 + 0) * 64 + j];
        float ay = A_v[(nl * 3 + 1) * 64 + j];
        float az = A_v[(nl * 3 + 2) * 64 + j];
        float4 wls = *(const float4*)&Wb0[j * 64 + fi * 4];
        float4 wlv = *(const float4*)&Wb1[j * 64 + fi * 4];
        s2.x  = fmaf(a, wls.x, s2.x);   s2.y  = fmaf(a, wls.y, s2.y);
        s2.z  = fmaf(a, wls.z, s2.z);   s2.w  = fmaf(a, wls.w, s2.w);
        v2x.x = fmaf(ax, wlv.x, v2x.x); v2x.y = fmaf(ax, wlv.y, v2x.y);
        v2x.z = fmaf(ax, wlv.z, v2x.z); v2x.w = fmaf(ax, wlv.w, v2x.w);
        v2y.x = fmaf(ay, wlv.x, v2y.x); v2y.y = fmaf(ay, wlv.y, v2y.y);
        v2y.z = fmaf(ay, wlv.z, v2y.z); v2y.w = fmaf(ay, wlv.w, v2y.w);
        v2z.x = fmaf(az, wlv.x, v2z.x); v2z.y = fmaf(az, wlv.y, v2z.y);
        v2z.z = fmaf(az, wlv.z, v2z.z); v2z.w = fmaf(az, wlv.w, v2z.w);
    }

    int z = spec[n];

    // Skip connection (LAYER>0): per-species linear, weights straight from L2
    float4 scS  = make_float4(0.f, 0.f, 0.f, 0.f);
    float4 scVx = scS, scVy = scS, scVz = scS;
    if (LAYER > 0) {
        const float* Ss = skipS + z * FF * FF;
        const float* Sv = skipV + z * FF * FF;
#pragma unroll 4
        for (int j = 0; j < FF; j++) {
            float b  = B_s[nl * 64 + j];
            float bx = B_v[(nl * 3 + 0) * 64 + j];
            float by = B_v[(nl * 3 + 1) * 64 + j];
            float bz = B_v[(nl * 3 + 2) * 64 + j];
            float4 aa = *(const float4*)&Ss[j * 64 + fi * 4];
            float4 bb = *(const float4*)&Sv[j * 64 + fi * 4];
            scS.x  = fmaf(b, aa.x, scS.x);   scS.y  = fmaf(b, aa.y, scS.y);
            scS.z  = fmaf(b, aa.z, scS.z);   scS.w  = fmaf(b, aa.w, scS.w);
            scVx.x = fmaf(bx, bb.x, scVx.x); scVx.y = fmaf(bx, bb.y, scVx.y);
            scVx.z = fmaf(bx, bb.z, scVx.z); scVx.w = fmaf(bx, bb.w, scVx.w);
            scVy.x = fmaf(by, bb.x, scVy.x); scVy.y = fmaf(by, bb.y, scVy.y);
            scVy.z = fmaf(by, bb.z, scVy.z); scVy.w = fmaf(by, bb.w, scVy.w);
            scVz.x = fmaf(bz, bb.x, scVz.x); scVz.y = fmaf(bz, bb.y, scVz.y);
            scVz.z = fmaf(bz, bb.z, scVz.z); scVz.w = fmaf(bz, bb.w, scVz.w);
        }
    }

    // Product basis (per channel)
    const float* pp = pwL + z * 9 * FF;
    float4 P[9];
#pragma unroll
    for (int k = 0; k < 9; k++) P[k] = *(const float4*)&pp[k * FF + fi * 4];
    float4 ps, pvx, pvy, pvz;
#pragma unroll
    for (int c = 0; c < 4; c++) {
        float S  = (&s2.x)[c];
        float VX = (&v2x.x)[c], VY = (&v2y.x)[c], VZ = (&v2z.x)[c];
        float vv = VX * VX + VY * VY + VZ * VZ;
        float S2 = S * S;
        float psv = (&P[0].x)[c] * S + (&P[1].x)[c] * S2 + (&P[2].x)[c] * vv
                  + (&P[3].x)[c] * S2 * S + (&P[4].x)[c] * S * vv;
        float pf  = (&P[5].x)[c] + (&P[6].x)[c] * S + (&P[7].x)[c] * S2 + (&P[8].x)[c] * vv;
        (&ps.x)[c]  = psv;
        (&pvx.x)[c] = pf * VX;
        (&pvy.x)[c] = pf * VY;
        (&pvz.x)[c] = pf * VZ;
    }
    __syncthreads();

    // Swap weights -> Wps/Wpv, write product basis into A buffers
    {
        const float4* a4 = (const float4*)WpsL;
        const float4* b4 = (const float4*)WpvL;
        float4* d0 = (float4*)Wb0;
        float4* d1 = (float4*)Wb1;
        for (int i = t; i < 1024; i += 256) { d0[i] = a4[i]; d1[i] = b4[i]; }
    }
    *(float4*)&A_s[nl * 64 + fi * 4] = ps;
    *(float4*)&A_v[(nl * 3 + 0) * 64 + fi * 4] = pvx;
    *(float4*)&A_v[(nl * 3 + 1) * 64 + fi * 4] = pvy;
    *(float4*)&A_v[(nl * 3 + 2) * 64 + fi * 4] = pvz;
    __syncthreads();

    // Phase 2: sN = ps @ Wps (+skip) ; vN = pv @ Wpv (+skip)
    float4 sN  = scS;
    float4 vNx = scVx, vNy = scVy, vNz = scVz;
#pragma unroll 4
    for (int j = 0; j < FF; j++) {
        float a  = A_s[nl * 64 + j];
        float ax = A_v[(nl * 3 + 0) * 64 + j];
        float ay = A_v[(nl * 3 + 1) * 64 + j];
        float az = A_v[(nl * 3 + 2) * 64 + j];
        float4 wps = *(const float4*)&Wb0[j * 64 + fi * 4];
        float4 wpv = *(const float4*)&Wb1[j * 64 + fi * 4];
        sN.x  = fmaf(a, wps.x, sN.x);   sN.y  = fmaf(a, wps.y, sN.y);
        sN.z  = fmaf(a, wps.z, sN.z);   sN.w  = fmaf(a, wps.w, sN.w);
        vNx.x = fmaf(ax, wpv.x, vNx.x); vNx.y = fmaf(ax, wpv.y, vNx.y);
        vNx.z = fmaf(ax, wpv.z, vNx.z); vNx.w = fmaf(ax, wpv.w, vNx.w);
        vNy.x = fmaf(ay, wpv.x, vNy.x); vNy.y = fmaf(ay, wpv.y, vNy.y);
        vNy.z = fmaf(ay, wpv.z, vNy.z); vNy.w = fmaf(ay, wpv.w, vNy.w);
        vNz.x = fmaf(az, wpv.x, vNz.x); vNz.y = fmaf(az, wpv.y, vNz.y);
        vNz.z = fmaf(az, wpv.z, vNz.z); vNz.w = fmaf(az, wpv.w, vNz.w);
    }

    if (LAYER < LL - 1) {
        ((float4*)sNew)[n * 16 + fi] = sN;
        ((float4*)vNew)[(n * 3 + 0) * 16 + fi] = vNx;
        ((float4*)vNew)[(n * 3 + 1) * 16 + fi] = vNy;
        ((float4*)vNew)[(n * 3 + 2) * 16 + fi] = vNz;
    }

    // Readout
    if (LAYER == 0) {
        // linear readout from registers: partial dot + 16-lane xor reduce
        float4 wr = *(const float4*)&Wread0[fi * 4];
        float part = sN.x * wr.x + sN.y * wr.y + sN.z * wr.z + sN.w * wr.w;
#pragma unroll
        for (int o = 8; o > 0; o >>= 1)
            part += __shfl_xor_sync(0xffffffffu, part, o);
        if (fi == 0) out[n * LL + 0] = part;
    } else {
        // need full sN vector per node -> stage in B_s (old values fully consumed)
        *(float4*)&B_s[nl * 64 + fi * 4] = sN;
        __syncthreads();
        int h = fi;
        float a = 0.f;
#pragma unroll 8
        for (int g = 0; g < FF; g++)
            a = fmaf(B_s[nl * 64 + g], Wr1a[g * HH + h], a);
        float sil = a / (1.f + __expf(-a));
        float part = sil * Wr1b[h];
#pragma unroll
        for (int o = 8; o > 0; o >>= 1)
            part += __shfl_xor_sync(0xffffffffu, part, o);
        if (fi == 0) out[n * LL + (LL - 1)] = part;
    }
}

// ---------------------------------------------------------------------------
extern "C" void kernel_launch(void* const* d_in, const int* in_sizes, int n_in,
                              void* d_out, int out_size) {
    const float* vectors = (const float*)d_in[0];
    const float* embed_s = (const float*)d_in[1];
    const float* Wr      = (const float*)d_in[2];
    const float* Wls     = (const float*)d_in[3];
    const float* Wlv     = (const float*)d_in[4];
    const float* skip_s  = (const float*)d_in[5];
    const float* skip_v  = (const float*)d_in[6];
    const float* pw      = (const float*)d_in[7];
    const float* Wps     = (const float*)d_in[8];
    const float* Wpv     = (const float*)d_in[9];
    const float* Wread0  = (const float*)d_in[10];
    const float* Wr1a    = (const float*)d_in[11];
    const float* Wr1b    = (const float*)d_in[12];
    const int*   senders   = (const int*)d_in[13];
    const int*   receivers = (const int*)d_in[14];
    const int*   species   = (const int*)d_in[15];
    float* out = (float*)d_out;

    void *p_sA, *p_vA, *p_sB, *p_vB;
    cudaGetSymbolAddress(&p_sA, g_sA);
    cudaGetSymbolAddress(&p_vA, g_vA);
    cudaGetSymbolAddress(&p_sB, g_sB);
    cudaGetSymbolAddress(&p_vB, g_vB);
    float* sA = (float*)p_sA;
    float* vA = (float*)p_vA;
    float* sB = (float*)p_sB;
    float* vB = (float*)p_vB;

    const int NODE_SMEM = 16384 * 4;  // 64KB
    static bool attrSet = false;
    if (!attrSet) {
        cudaFuncSetAttribute(nodeK<0>, cudaFuncAttributeMaxDynamicSharedMemorySize, NODE_SMEM);
        cudaFuncSetAttribute(nodeK<1>, cudaFuncAttributeMaxDynamicSharedMemorySize, NODE_SMEM);
        attrSet = true;
    }

    initK<<<(NN * FF / 4 + 255) / 256, 256>>>(embed_s, species);

    // ---- Layer 0 ----
    edgeK<true><<<EE / 16, 256>>>(vectors, Wr, senders, receivers, sA, vA);
    nodeK<0><<<NN / 16, 256, NODE_SMEM>>>(sA, vA, sB, vB, species,
                              Wls, Wlv, pw, Wps, Wpv,
                              skip_s, skip_v, Wread0, Wr1a, Wr1b, out);

    // ---- Layer 1 ----
    edgeK<false><<<EE / 16, 256>>>(vectors, Wr + NBB * 5 * FF, senders, receivers, sB, vB);
    nodeK<1><<<NN / 16, 256, NODE_SMEM>>>(sB, vB, sA, vA, species,
                              Wls + FF * FF, Wlv + FF * FF,
                              pw + ZZ * 9 * FF,
                              Wps + FF * FF, Wpv + FF * FF,
                              skip_s, skip_v, Wread0, Wr1a, Wr1b, out);
}

// round 4
// speedup vs baseline: 2.2404x; 1.0768x over previous
#include <cuda_runtime.h>
#include <math.h>

#define NN   32768
#define EE   262144
#define FF   64
#define ZZ   10
#define NBB  8
#define LL   2
#define HH   16

#define EPSC   0.24253562503633297f
#define SQRT2C 1.4142135623730951f
#define PI_F   3.14159265358979323846f

// Scratch (device globals; allocation-free), 16B-aligned for float4 access
__device__ __align__(16) float g_sA[NN * FF];
__device__ __align__(16) float g_vA[NN * 3 * FF];
__device__ __align__(16) float g_sB[NN * FF];
__device__ __align__(16) float g_vB[NN * 3 * FF];
__device__ __align__(16) float g_aggS[NN * FF];
__device__ __align__(16) float g_aggV[NN * 3 * FF];

__device__ __forceinline__ void redAdd4(float* p, float a, float b, float c, float d) {
    asm volatile("red.global.add.v4.f32 [%0], {%1, %2, %3, %4};"
                 :: "l"(p), "f"(a), "f"(b), "f"(c), "f"(d) : "memory");
}

// ---------------------------------------------------------------------------
// Init: s = embed_s[spec], v = 0, agg = 0   (float4 wide)
// ---------------------------------------------------------------------------
__global__ void initK(const float* __restrict__ embed, const int* __restrict__ spec) {
    int i = blockIdx.x * 256 + threadIdx.x;          // float4 index over [N*F/4]
    if (i >= NN * FF / 4) return;
    int n  = i >> 4;
    int f4 = i & 15;
    const float4* e4 = (const float4*)embed;
    ((float4*)g_sA)[i] = e4[spec[n] * 16 + f4];
    float4 z = make_float4(0.f, 0.f, 0.f, 0.f);
    ((float4*)g_aggS)[i] = z;
#pragma unroll
    for (int k = 0; k < 3; k++) {
        ((float4*)g_vA)[(n * 3 + k) * 16 + f4]   = z;
        ((float4*)g_aggV)[(n * 3 + k) * 16 + f4] = z;
    }
}

// ---------------------------------------------------------------------------
// Edge kernel: 256 threads = 16 slots x 16 channel-groups, 2 edges per thread.
// The Wr shared-memory sweep is amortized over both edges (halves LDS traffic);
// for FIRST (v==0) only paths 0 and 2 are computed (16 instead of 40 LDS).
// ---------------------------------------------------------------------------
template <bool FIRST>
__global__ void __launch_bounds__(256) edgeK(
                      const float* __restrict__ vec,
                      const float* __restrict__ WrL,      // [8,320]
                      const int*   __restrict__ snd,
                      const int*   __restrict__ rcv,
                      const float* __restrict__ sIn,      // [N,F]
                      const float* __restrict__ vIn) {    // [N,3,F]
    __shared__ float WrS[NBB * 5 * FF];   // 2560 floats = 10KB
    int t = threadIdx.x;
    {
        const float4* src = (const float4*)WrL;
        float4* dst = (float4*)WrS;
        for (int i = t; i < NBB * 5 * FF / 4; i += 256) dst[i] = src[i];
    }
    __syncthreads();

    int slot = t >> 4;
    int fi   = t & 15;                    // channels 4*fi .. 4*fi+3
    int base = blockIdx.x * 32 + slot * 2;

    int   sidx[2], ridx[2];
    float y[2][3];
    float rb[2][8];

#pragma unroll
    for (int u = 0; u < 2; u++) {
        int e = base + u;
        sidx[u] = snd[e];
        ridx[u] = rcv[e];
        float vx = vec[e * 3 + 0];
        float vy = vec[e * 3 + 1];
        float vz = vec[e * 3 + 2];
        float r  = sqrtf(vx * vx + vy * vy + vz * vz + 1e-12f);
        float rc = fmaxf(r, 1e-6f);
        float env = 0.f;
        if (r < 1.f) {
            float r2 = r * r;
            float r6 = r2 * r2 * r2;
            env = 1.f - 28.f * r6 + 48.f * r6 * r - 21.f * r6 * r2;
        }
        float scale = SQRT2C * env / rc;
        float s1, c1;
        __sincosf(PI_F * rc, &s1, &c1);
        float c2 = 2.f * c1;
        float sp = s1, spp = 0.f;
        rb[u][0] = s1 * scale;
#pragma unroll
        for (int n = 1; n < NBB; n++) {
            float sn = c2 * sp - spp;
            rb[u][n] = sn * scale;
            spp = sp; sp = sn;
        }
        float iy = 1.f / r;
        y[u][0] = vx * iy; y[u][1] = vy * iy; y[u][2] = vz * iy;
    }

    // Radial-weight sweep, shared across both edges
    const int NP = FIRST ? 2 : 5;
    float4 w[2][5];
#pragma unroll
    for (int u = 0; u < 2; u++)
#pragma unroll
        for (int p = 0; p < 5; p++) w[u][p] = make_float4(0.f, 0.f, 0.f, 0.f);

#pragma unroll
    for (int n = 0; n < NBB; n++) {
#pragma unroll
        for (int pi = 0; pi < NP; pi++) {
            int p = FIRST ? (pi * 2) : pi;      // FIRST: paths 0,2
            float4 ww = *(const float4*)&WrS[n * 320 + p * 64 + fi * 4];
#pragma unroll
            for (int u = 0; u < 2; u++) {
                float r0 = rb[u][n];
                w[u][p].x = fmaf(r0, ww.x, w[u][p].x);
                w[u][p].y = fmaf(r0, ww.y, w[u][p].y);
                w[u][p].z = fmaf(r0, ww.z, w[u][p].z);
                w[u][p].w = fmaf(r0, ww.w, w[u][p].w);
            }
        }
    }

    // Messages + scatter
#pragma unroll
    for (int u = 0; u < 2; u++) {
        int s_ = sidx[u], r_ = ridx[u];
        float y0 = y[u][0], y1 = y[u][1], y2 = y[u][2];
        float4 ss = *(const float4*)&sIn[s_ * FF + fi * 4];

        float4 m0, m1x, m1y, m1z;
        if (FIRST) {
#pragma unroll
            for (int c = 0; c < 4; c++) {
                float SS = (&ss.x)[c];
                (&m0.x)[c]  = (&w[u][0].x)[c] * SS;
                float cc    = (&w[u][2].x)[c] * SS;
                (&m1x.x)[c] = cc * y0;
                (&m1y.x)[c] = cc * y1;
                (&m1z.x)[c] = cc * y2;
            }
        } else {
            float4 vsx = *(const float4*)&vIn[(s_ * 3 + 0) * FF + fi * 4];
            float4 vsy = *(const float4*)&vIn[(s_ * 3 + 1) * FF + fi * 4];
            float4 vsz = *(const float4*)&vIn[(s_ * 3 + 2) * FF + fi * 4];
#pragma unroll
            for (int c = 0; c < 4; c++) {
                float VX = (&vsx.x)[c], VY = (&vsy.x)[c], VZ = (&vsz.x)[c];
                float SS = (&ss.x)[c];
                float w0 = (&w[u][0].x)[c], w1 = (&w[u][1].x)[c], w2 = (&w[u][2].x)[c];
                float w3 = (&w[u][3].x)[c], w4 = (&w[u][4].x)[c];
                float dot = VX * y0 + VY * y1 + VZ * y2;
                (&m0.x)[c]  = w0 * SS + w1 * dot;
                float cc = w2 * SS;
                (&m1x.x)[c] = cc * y0 + w3 * VX + w4 * (VY * y2 - VZ * y1);
                (&m1y.x)[c] = cc * y1 + w3 * VY + w4 * (VZ * y0 - VX * y2);
                (&m1z.x)[c] = cc * y2 + w3 * VZ + w4 * (VX * y1 - VY * y0);
            }
        }

        redAdd4(&g_aggS[r_ * FF + fi * 4], m0.x, m0.y, m0.z, m0.w);
        redAdd4(&g_aggV[(r_ * 3 + 0) * FF + fi * 4], m1x.x, m1x.y, m1x.z, m1x.w);
        redAdd4(&g_aggV[(r_ * 3 + 1) * FF + fi * 4], m1y.x, m1y.y, m1y.z, m1y.w);
        redAdd4(&g_aggV[(r_ * 3 + 2) * FF + fi * 4], m1z.x, m1z.y, m1z.z, m1z.w);
    }
}

// ---------------------------------------------------------------------------
// Node kernel: 16 nodes/block x 16 threads/node (4 channels each, float4)
// ---------------------------------------------------------------------------
template <int LAYER>
__global__ void nodeK(const float* __restrict__ sOld,
                      const float* __restrict__ vOld,
                      float* __restrict__ sNew,
                      float* __restrict__ vNew,
                      const int*   __restrict__ spec,
                      const float* __restrict__ WlsL,
                      const float* __restrict__ WlvL,
                      const float* __restrict__ pwL,    // [Z,9,F]
                      const float* __restrict__ WpsL,
                      const float* __restrict__ WpvL,
                      const float* __restrict__ skipS,  // [Z,F,F]
                      const float* __restrict__ skipV,
                      const float* __restrict__ Wread0,
                      const float* __restrict__ Wr1a,   // [F,H]
                      const float* __restrict__ Wr1b,   // [H]
                      float* __restrict__ out) {
    extern __shared__ float sm[];
    float* Wb0 = sm;                 // 4096
    float* Wb1 = sm + 4096;          // 4096
    float* A_s = sm + 8192;          // 1024
    float* A_v = sm + 9216;          // 3072
    float* B_s = sm + 12288;         // 1024
    float* B_v = sm + 13312;         // 3072  (total 16384 floats = 64KB)

    int t  = threadIdx.x;
    int nl = t >> 4;
    int fi = t & 15;
    int n  = blockIdx.x * 16 + nl;

    {
        const float4* a4 = (const float4*)WlsL;
        const float4* b4 = (const float4*)WlvL;
        float4* d0 = (float4*)Wb0;
        float4* d1 = (float4*)Wb1;
        for (int i = t; i < 1024; i += 256) { d0[i] = a4[i]; d1[i] = b4[i]; }
    }
    {
        float4 a = ((const float4*)g_aggS)[n * 16 + fi];
        a.x *= EPSC; a.y *= EPSC; a.z *= EPSC; a.w *= EPSC;
        *(float4*)&A_s[nl * 64 + fi * 4] = a;
#pragma unroll
        for (int k = 0; k < 3; k++) {
            float4 v = ((const float4*)g_aggV)[(n * 3 + k) * 16 + fi];
            v.x *= EPSC; v.y *= EPSC; v.z *= EPSC; v.w *= EPSC;
            *(float4*)&A_v[(nl * 3 + k) * 64 + fi * 4] = v;
        }
        float4 z = make_float4(0.f, 0.f, 0.f, 0.f);
        if (LAYER == 0) {
            ((float4*)g_aggS)[n * 16 + fi] = z;
#pragma unroll
            for (int k = 0; k < 3; k++) ((float4*)g_aggV)[(n * 3 + k) * 16 + fi] = z;
        }
        if (LAYER > 0) {
            *(float4*)&B_s[nl * 64 + fi * 4] = ((const float4*)sOld)[n * 16 + fi];
#pragma unroll
            for (int k = 0; k < 3; k++)
                *(float4*)&B_v[(nl * 3 + k) * 64 + fi * 4] =
                    ((const float4*)vOld)[(n * 3 + k) * 16 + fi];
        }
    }
    __syncthreads();

    float4 s2  = make_float4(0.f, 0.f, 0.f, 0.f);
    float4 v2x = s2, v2y = s2, v2z = s2;
#pragma unroll 4
    for (int j = 0; j < FF; j++) {
        float a  = A_s[nl * 64 + j];
        float ax = A_v[(nl * 3 + 0) * 64 + j];
        float ay = A_v[(nl * 3 + 1) * 64 + j];
        float az = A_v[(nl * 3 + 2) * 64 + j];
        float4 wls = *(const float4*)&Wb0[j * 64 + fi * 4];
        float4 wlv = *(const float4*)&Wb1[j * 64 + fi * 4];
        s2.x  = fmaf(a, wls.x, s2.x);   s2.y  = fmaf(a, wls.y, s2.y);
        s2.z  = fmaf(a, wls.z, s2.z);   s2.w  = fmaf(a, wls.w, s2.w);
        v2x.x = fmaf(ax, wlv.x, v2x.x); v2x.y = fmaf(ax, wlv.y, v2x.y);
        v2x.z = fmaf(ax, wlv.z, v2x.z); v2x.w = fmaf(ax, wlv.w, v2x.w);
        v2y.x = fmaf(ay, wlv.x, v2y.x); v2y.y = fmaf(ay, wlv.y, v2y.y);
        v2y.z = fmaf(ay, wlv.z, v2y.z); v2y.w = fmaf(ay, wlv.w, v2y.w);
        v2z.x = fmaf(az, wlv.x, v2z.x); v2z.y = fmaf(az, wlv.y, v2z.y);
        v2z.z = fmaf(az, wlv.z, v2z.z); v2z.w = fmaf(az, wlv.w, v2z.w);
    }

    int z = spec[n];

    float4 scS  = make_float4(0.f, 0.f, 0.f, 0.f);
    float4 scVx = scS, scVy = scS, scVz = scS;
    if (LAYER > 0) {
        const float* Ss = skipS + z * FF * FF;
        const float* Sv = skipV + z * FF * FF;
#pragma unroll 4
        for (int j = 0; j < FF; j++) {
            float b  = B_s[nl * 64 + j];
            float bx = B_v[(nl * 3 + 0) * 64 + j];
            float by = B_v[(nl * 3 + 1) * 64 + j];
            float bz = B_v[(nl * 3 + 2) * 64 + j];
            float4 aa = *(const float4*)&Ss[j * 64 + fi * 4];
            float4 bb = *(const float4*)&Sv[j * 64 + fi * 4];
            scS.x  = fmaf(b, aa.x, scS.x);   scS.y  = fmaf(b, aa.y, scS.y);
            scS.z  = fmaf(b, aa.z, scS.z);   scS.w  = fmaf(b, aa.w, scS.w);
            scVx.x = fmaf(bx, bb.x, scVx.x); scVx.y = fmaf(bx, bb.y, scVx.y);
            scVx.z = fmaf(bx, bb.z, scVx.z); scVx.w = fmaf(bx, bb.w, scVx.w);
            scVy.x = fmaf(by, bb.x, scVy.x); scVy.y = fmaf(by, bb.y, scVy.y);
            scVy.z = fmaf(by, bb.z, scVy.z); scVy.w = fmaf(by, bb.w, scVy.w);
            scVz.x = fmaf(bz, bb.x, scVz.x); scVz.y = fmaf(bz, bb.y, scVz.y);
            scVz.z = fmaf(bz, bb.z, scVz.z); scVz.w = fmaf(bz, bb.w, scVz.w);
        }
    }

    const float* pp = pwL + z * 9 * FF;
    float4 P[9];
#pragma unroll
    for (int k = 0; k < 9; k++) P[k] = *(const float4*)&pp[k * FF + fi * 4];
    float4 ps, pvx, pvy, pvz;
#pragma unroll
    for (int c = 0; c < 4; c++) {
        float S  = (&s2.x)[c];
        float VX = (&v2x.x)[c], VY = (&v2y.x)[c], VZ = (&v2z.x)[c];
        float vv = VX * VX + VY * VY + VZ * VZ;
        float S2 = S * S;
        float psv = (&P[0].x)[c] * S + (&P[1].x)[c] * S2 + (&P[2].x)[c] * vv
                  + (&P[3].x)[c] * S2 * S + (&P[4].x)[c] * S * vv;
        float pf  = (&P[5].x)[c] + (&P[6].x)[c] * S + (&P[7].x)[c] * S2 + (&P[8].x)[c] * vv;
        (&ps.x)[c]  = psv;
        (&pvx.x)[c] = pf * VX;
        (&pvy.x)[c] = pf * VY;
        (&pvz.x)[c] = pf * VZ;
    }
    __syncthreads();

    {
        const float4* a4 = (const float4*)WpsL;
        const float4* b4 = (const float4*)WpvL;
        float4* d0 = (float4*)Wb0;
        float4* d1 = (float4*)Wb1;
        for (int i = t; i < 1024; i += 256) { d0[i] = a4[i]; d1[i] = b4[i]; }
    }
    *(float4*)&A_s[nl * 64 + fi * 4] = ps;
    *(float4*)&A_v[(nl * 3 + 0) * 64 + fi * 4] = pvx;
    *(float4*)&A_v[(nl * 3 + 1) * 64 + fi * 4] = pvy;
    *(float4*)&A_v[(nl * 3 + 2) * 64 + fi * 4] = pvz;
    __syncthreads();

    float4 sN  = scS;
    float4 vNx = scVx, vNy = scVy, vNz = scVz;
#pragma unroll 4
    for (int j = 0; j < FF; j++) {
        float a  = A_s[nl * 64 + j];
        float ax = A_v[(nl * 3 + 0) * 64 + j];
        float ay = A_v[(nl * 3 + 1) * 64 + j];
        float az = A_v[(nl * 3 + 2) * 64 + j];
        float4 wps = *(const float4*)&Wb0[j * 64 + fi * 4];
        float4 wpv = *(const float4*)&Wb1[j * 64 + fi * 4];
        sN.x  = fmaf(a, wps.x, sN.x);   sN.y  = fmaf(a, wps.y, sN.y);
        sN.z  = fmaf(a, wps.z, sN.z);   sN.w  = fmaf(a, wps.w, sN.w);
        vNx.x = fmaf(ax, wpv.x, vNx.x); vNx.y = fmaf(ax, wpv.y, vNx.y);
        vNx.z = fmaf(ax, wpv.z, vNx.z); vNx.w = fmaf(ax, wpv.w, vNx.w);
        vNy.x = fmaf(ay, wpv.x, vNy.x); vNy.y = fmaf(ay, wpv.y, vNy.y);
        vNy.z = fmaf(ay, wpv.z, vNy.z); vNy.w = fmaf(ay, wpv.w, vNy.w);
        vNz.x = fmaf(az, wpv.x, vNz.x); vNz.y = fmaf(az, wpv.y, vNz.y);
        vNz.z = fmaf(az, wpv.z, vNz.z); vNz.w = fmaf(az, wpv.w, vNz.w);
    }

    if (LAYER < LL - 1) {
        ((float4*)sNew)[n * 16 + fi] = sN;
        ((float4*)vNew)[(n * 3 + 0) * 16 + fi] = vNx;
        ((float4*)vNew)[(n * 3 + 1) * 16 + fi] = vNy;
        ((float4*)vNew)[(n * 3 + 2) * 16 + fi] = vNz;
    }

    if (LAYER == 0) {
        float4 wr = *(const float4*)&Wread0[fi * 4];
        float part = sN.x * wr.x + sN.y * wr.y + sN.z * wr.z + sN.w * wr.w;
#pragma unroll
        for (int o = 8; o > 0; o >>= 1)
            part += __shfl_xor_sync(0xffffffffu, part, o);
        if (fi == 0) out[n * LL + 0] = part;
    } else {
        *(float4*)&B_s[nl * 64 + fi * 4] = sN;
        __syncthreads();
        int h = fi;
        float a = 0.f;
#pragma unroll 8
        for (int g = 0; g < FF; g++)
            a = fmaf(B_s[nl * 64 + g], Wr1a[g * HH + h], a);
        float sil = a / (1.f + __expf(-a));
        float part = sil * Wr1b[h];
#pragma unroll
        for (int o = 8; o > 0; o >>= 1)
            part += __shfl_xor_sync(0xffffffffu, part, o);
        if (fi == 0) out[n * LL + (LL - 1)] = part;
    }
}

// ---------------------------------------------------------------------------
extern "C" void kernel_launch(void* const* d_in, const int* in_sizes, int n_in,
                              void* d_out, int out_size) {
    const float* vectors = (const float*)d_in[0];
    const float* embed_s = (const float*)d_in[1];
    const float* Wr      = (const float*)d_in[2];
    const float* Wls     = (const float*)d_in[3];
    const float* Wlv     = (const float*)d_in[4];
    const float* skip_s  = (const float*)d_in[5];
    const float* skip_v  = (const float*)d_in[6];
    const float* pw      = (const float*)d_in[7];
    const float* Wps     = (const float*)d_in[8];
    const float* Wpv     = (const float*)d_in[9];
    const float* Wread0  = (const float*)d_in[10];
    const float* Wr1a    = (const float*)d_in[11];
    const float* Wr1b    = (const float*)d_in[12];
    const int*   senders   = (const int*)d_in[13];
    const int*   receivers = (const int*)d_in[14];
    const int*   species   = (const int*)d_in[15];
    float* out = (float*)d_out;

    void *p_sA, *p_vA, *p_sB, *p_vB;
    cudaGetSymbolAddress(&p_sA, g_sA);
    cudaGetSymbolAddress(&p_vA, g_vA);
    cudaGetSymbolAddress(&p_sB, g_sB);
    cudaGetSymbolAddress(&p_vB, g_vB);
    float* sA = (float*)p_sA;
    float* vA = (float*)p_vA;
    float* sB = (float*)p_sB;
    float* vB = (float*)p_vB;

    const int NODE_SMEM = 16384 * 4;  // 64KB
    static bool attrSet = false;
    if (!attrSet) {
        cudaFuncSetAttribute(nodeK<0>, cudaFuncAttributeMaxDynamicSharedMemorySize, NODE_SMEM);
        cudaFuncSetAttribute(nodeK<1>, cudaFuncAttributeMaxDynamicSharedMemorySize, NODE_SMEM);
        attrSet = true;
    }

    initK<<<(NN * FF / 4 + 255) / 256, 256>>>(embed_s, species);

    // ---- Layer 0 ----
    edgeK<true><<<EE / 32, 256>>>(vectors, Wr, senders, receivers, sA, vA);
    nodeK<0><<<NN / 16, 256, NODE_SMEM>>>(sA, vA, sB, vB, species,
                              Wls, Wlv, pw, Wps, Wpv,
                              skip_s, skip_v, Wread0, Wr1a, Wr1b, out);

    // ---- Layer 1 ----
    edgeK<false><<<EE / 32, 256>>>(vectors, Wr + NBB * 5 * FF, senders, receivers, sB, vB);
    nodeK<1><<<NN / 16, 256, NODE_SMEM>>>(sB, vB, sA, vA, species,
                              Wls + FF * FF, Wlv + FF * FF,
                              pw + ZZ * 9 * FF,
                              Wps + FF * FF, Wpv + FF * FF,
                              skip_s, skip_v, Wread0, Wr1a, Wr1b, out);
}